// round 10
// baseline (speedup 1.0000x reference)
#include <cuda_runtime.h>
#include <cuda_bf16.h>
#include <math.h>

// Problem constants
#define BB   512
#define NN   101
#define EE   128
#define MM   8
#define DKK  16
#define TT   (BB * NN)        // 51712 = 202 * 256
#define FF   (4 * EE)         // 512
#define QKV  (3 * EE)         // 384
#define EPS  1e-5f

typedef unsigned long long ull;

// ---------------- device scratch ----------------
__device__ float g_x[TT * EE];
__device__ float g_qkv[TT * QKV];
__device__ float g_o[TT * EE];
__device__ float g_t[TT * EE];
__device__ float g_h[TT * FF];
__device__ float g_wqkv[3 * EE * QKV];
__device__ float g_bqkv[3 * QKV];
__device__ float g_ps [808 * EE];
__device__ float g_ps2[808 * EE];
__device__ float g_scale[EE];
__device__ float g_shift[EE];

// ---------------- f32x2 helpers ----------------
__device__ __forceinline__ ull fma2(ull a, ull b, ull c)
{
    ull d;
    asm("fma.rn.f32x2 %0, %1, %2, %3;" : "=l"(d) : "l"(a), "l"(b), "l"(c));
    return d;
}
__device__ __forceinline__ ull pack2(float x, float y)
{
    ull r;
    asm("mov.b64 %0, {%1, %2};" : "=l"(r) : "f"(x), "f"(y));
    return r;
}
__device__ __forceinline__ float2 unpack2(ull v)
{
    float2 r;
    asm("mov.b64 {%0, %1}, %2;" : "=f"(r.x), "=f"(r.y) : "l"(v));
    return r;
}

// ---------------- embedding ----------------
__global__ void embed_kernel(const float* __restrict__ s, const int* __restrict__ d,
                             const float* __restrict__ e_w, const float* __restrict__ e_b,
                             const float* __restrict__ ep_w, const float* __restrict__ ep_b,
                             float* __restrict__ x)
{
    int idx = blockIdx.x * 256 + threadIdx.x;
    if (idx >= TT * EE) return;
    int e = idx & (EE - 1);
    int t = idx >> 7;
    int n = t % NN;
    int b = t / NN;
    float s0 = s[(b * NN + n) * 2 + 0];
    float s1 = s[(b * NN + n) * 2 + 1];
    float out;
    if (n == 0) {
        out = s0 * ep_w[e] + s1 * ep_w[EE + e] + ep_b[e];
    } else {
        float dd = (float)d[b * NN + n];
        out = s0 * e_w[e] + s1 * e_w[EE + e] + dd * e_w[2 * EE + e] + e_b[e];
    }
    x[idx] = out;
}

// ---------------- pack QKV weights ----------------
__global__ void pack_qkv(const float* __restrict__ Wq, const float* __restrict__ Wk,
                         const float* __restrict__ Wv, const float* __restrict__ bq,
                         const float* __restrict__ bk, const float* __restrict__ bv,
                         float* __restrict__ wout, float* __restrict__ bout)
{
    int idx = blockIdx.x * 256 + threadIdx.x;
    int total = 3 * EE * QKV;
    if (idx < total) {
        int i = idx / (EE * QKV);
        int r = idx % (EE * QKV);
        int k = r / QKV;
        int j = r % QKV;
        float v;
        if (j < EE)            v = Wq[(size_t)i * EE * EE + k * EE + j];
        else if (j < 2 * EE)   v = Wk[(size_t)i * EE * EE + k * EE + (j - EE)];
        else                   v = Wv[(size_t)i * EE * EE + k * EE + (j - 2 * EE)];
        wout[idx] = v;
    }
    if (idx < 3 * QKV) {
        int i = idx / QKV;
        int j = idx % QKV;
        float v;
        if (j < EE)            v = bq[i * EE + j];
        else if (j < 2 * EE)   v = bk[i * EE + (j - EE)];
        else                   v = bv[i * EE + (j - 2 * EE)];
        bout[idx] = v;
    }
}

// ---------------- GEMM v4: 256x128 block tile, 16x8 microtile, f32x2 -------
// C = affA(A) @ W + bias [+ affR(res) | relu]
#define BMt 256
#define BNt 128
#define BKt 32
#define AS_S (BMt + 4)                         // 260 floats (rows stay 16B aligned)
#define SM_AS   (BKt * AS_S * 4)               // 33280 B
#define SM_BS   (BKt * BNt * 4)                // 16384 B
#define SM_SA   (512 * 4)                      // 2048 B
#define SM_GEMM (SM_AS + SM_BS + 2 * SM_SA)    // 53760 B

__global__ __launch_bounds__(256, 1) void gemm_ep(
    const float* __restrict__ A, const float* __restrict__ W,
    const float* __restrict__ bias, const float* __restrict__ res,
    float* __restrict__ C, int K, int Nout, int mode,
    const float* __restrict__ sA, const float* __restrict__ hA,
    const float* __restrict__ sR, const float* __restrict__ hR)
{
    extern __shared__ char smem[];
    float* As   = (float*)smem;                          // [BKt][AS_S]
    float* Bs   = (float*)(smem + SM_AS);                // [BKt][BNt]
    float* sAsm = (float*)(smem + SM_AS + SM_BS);
    float* hAsm = (float*)(smem + SM_AS + SM_BS + SM_SA);

    const int t0 = blockIdx.y * BMt;
    const int n0 = blockIdx.x * BNt;
    const int tid = threadIdx.x;
    const int tx = tid & 15;    // 16 col groups (cols tx*4 and 64+tx*4)
    const int ty = tid >> 4;    // 16 row groups (16 rows each)

    for (int i = tid; i < K; i += 256) {
        sAsm[i] = sA ? sA[i] : 1.0f;
        hAsm[i] = hA ? hA[i] : 0.0f;
    }
    __syncthreads();

    ull acc[16][4];
    #pragma unroll
    for (int r = 0; r < 16; r++)
        #pragma unroll
        for (int p = 0; p < 4; p++)
            acc[r][p] = pack2(0.f, 0.f);

    for (int k0 = 0; k0 < K; k0 += BKt) {
        // A tile: 256 rows x 32 k, affine applied, transposed into As
        #pragma unroll
        for (int p = 0; p < 8; p++) {
            int i   = p * 256 + tid;
            int row = i >> 3;            // 0..255
            int c4  = i & 7;             // 0..7
            int kc  = k0 + c4 * 4;
            float4 v = *reinterpret_cast<const float4*>(&A[(size_t)(t0 + row) * K + kc]);
            float4 sc = *reinterpret_cast<const float4*>(&sAsm[kc]);
            float4 sh = *reinterpret_cast<const float4*>(&hAsm[kc]);
            As[(c4 * 4 + 0) * AS_S + row] = fmaf(v.x, sc.x, sh.x);
            As[(c4 * 4 + 1) * AS_S + row] = fmaf(v.y, sc.y, sh.y);
            As[(c4 * 4 + 2) * AS_S + row] = fmaf(v.z, sc.z, sh.z);
            As[(c4 * 4 + 3) * AS_S + row] = fmaf(v.w, sc.w, sh.w);
        }
        // B tile: 32 k x 128 n  (1024 float4 over 256 threads -> 4 iterations)
        #pragma unroll
        for (int p = 0; p < 4; p++) {
            int i   = p * 256 + tid;     // 0..1023
            int row = i >> 5;            // 0..31
            int c4  = i & 31;            // 0..31
            *reinterpret_cast<float4*>(&Bs[row * BNt + c4 * 4]) =
                *reinterpret_cast<const float4*>(&W[(size_t)(k0 + row) * Nout + n0 + c4 * 4]);
        }
        __syncthreads();

        #pragma unroll 4
        for (int kk = 0; kk < BKt; kk++) {
            const float* ar = As + kk * AS_S + ty * 16;
            float4 a0 = *reinterpret_cast<const float4*>(ar + 0);
            float4 a1 = *reinterpret_cast<const float4*>(ar + 4);
            float4 a2 = *reinterpret_cast<const float4*>(ar + 8);
            float4 a3 = *reinterpret_cast<const float4*>(ar + 12);
            const float* bsk = Bs + kk * BNt;
            ulonglong2 b0 = *reinterpret_cast<const ulonglong2*>(bsk + tx * 4);
            ulonglong2 b1 = *reinterpret_cast<const ulonglong2*>(bsk + 64 + tx * 4);
            ull bp[4] = { b0.x, b0.y, b1.x, b1.y };
            float av[16] = { a0.x, a0.y, a0.z, a0.w, a1.x, a1.y, a1.z, a1.w,
                             a2.x, a2.y, a2.z, a2.w, a3.x, a3.y, a3.z, a3.w };
            #pragma unroll
            for (int r = 0; r < 16; r++) {
                ull ap = pack2(av[r], av[r]);
                #pragma unroll
                for (int p = 0; p < 4; p++)
                    acc[r][p] = fma2(ap, bp[p], acc[r][p]);
            }
        }
        __syncthreads();
    }

    // epilogue: thread rows = t0 + ty*16 + r ; cols tx*4 and 64+tx*4
    int colA = n0 + tx * 4;
    int colB = n0 + 64 + tx * 4;
    float4 bA = *reinterpret_cast<const float4*>(&bias[colA]);
    float4 bBv = *reinterpret_cast<const float4*>(&bias[colB]);
    float4 sRA = {1.f,1.f,1.f,1.f}, hRA = {0.f,0.f,0.f,0.f};
    float4 sRB = {1.f,1.f,1.f,1.f}, hRB = {0.f,0.f,0.f,0.f};
    if (mode == 1 && sR) {
        sRA = *reinterpret_cast<const float4*>(&sR[colA]);
        hRA = *reinterpret_cast<const float4*>(&hR[colA]);
        sRB = *reinterpret_cast<const float4*>(&sR[colB]);
        hRB = *reinterpret_cast<const float4*>(&hR[colB]);
    }
    #pragma unroll
    for (int r = 0; r < 16; r++) {
        int row = t0 + ty * 16 + r;
        float2 l0 = unpack2(acc[r][0]);
        float2 h0 = unpack2(acc[r][1]);
        float2 l1 = unpack2(acc[r][2]);
        float2 h1 = unpack2(acc[r][3]);
        float4 vA = { l0.x + bA.x, l0.y + bA.y, h0.x + bA.z, h0.y + bA.w };
        float4 vB = { l1.x + bBv.x, l1.y + bBv.y, h1.x + bBv.z, h1.y + bBv.w };
        if (mode == 1) {
            float4 rA = *reinterpret_cast<const float4*>(&res[(size_t)row * Nout + colA]);
            float4 rB = *reinterpret_cast<const float4*>(&res[(size_t)row * Nout + colB]);
            vA.x += fmaf(rA.x, sRA.x, hRA.x);
            vA.y += fmaf(rA.y, sRA.y, hRA.y);
            vA.z += fmaf(rA.z, sRA.z, hRA.z);
            vA.w += fmaf(rA.w, sRA.w, hRA.w);
            vB.x += fmaf(rB.x, sRB.x, hRB.x);
            vB.y += fmaf(rB.y, sRB.y, hRB.y);
            vB.z += fmaf(rB.z, sRB.z, hRB.z);
            vB.w += fmaf(rB.w, sRB.w, hRB.w);
        } else if (mode == 2) {
            vA.x = fmaxf(vA.x, 0.f); vA.y = fmaxf(vA.y, 0.f);
            vA.z = fmaxf(vA.z, 0.f); vA.w = fmaxf(vA.w, 0.f);
            vB.x = fmaxf(vB.x, 0.f); vB.y = fmaxf(vB.y, 0.f);
            vB.z = fmaxf(vB.z, 0.f); vB.w = fmaxf(vB.w, 0.f);
        }
        *reinterpret_cast<float4*>(&C[(size_t)row * Nout + colA]) = vA;
        *reinterpret_cast<float4*>(&C[(size_t)row * Nout + colB]) = vB;
    }
}

// ---------------- attention v2 (R7, measured 113us): single-pass f32x2 -----
__global__ __launch_bounds__(128) void attn_kernel(
    const float* __restrict__ QKVb, float* __restrict__ O)
{
    int bh = blockIdx.x;
    int b = bh >> 3;
    int h = bh & 7;
    const size_t rowbase = (size_t)b * NN;
    const int hq = h * DKK;

    __shared__ float4 ksh[NN][4];
    __shared__ float4 vsh[NN][4];
    int tid = threadIdx.x;
    for (int i = tid; i < NN * 4; i += 128) {
        int j = i >> 2, c = i & 3;
        ksh[j][c] = *reinterpret_cast<const float4*>(&QKVb[(rowbase + j) * QKV + EE     + hq + c * 4]);
        vsh[j][c] = *reinterpret_cast<const float4*>(&QKVb[(rowbase + j) * QKV + 2 * EE + hq + c * 4]);
    }
    __syncthreads();

    if (tid < NN) {
        ull qp[8];
        #pragma unroll
        for (int c = 0; c < 4; c++) {
            float4 q4 = *reinterpret_cast<const float4*>(&QKVb[(rowbase + tid) * QKV + hq + c * 4]);
            qp[c * 2 + 0] = pack2(q4.x * 0.25f, q4.y * 0.25f);
            qp[c * 2 + 1] = pack2(q4.z * 0.25f, q4.w * 0.25f);
        }
        const ull z2 = pack2(0.f, 0.f);
        ull oa[8];
        #pragma unroll
        for (int c = 0; c < 8; c++) oa[c] = z2;
        float l = 0.f;

        for (int j = 0; j < NN; j++) {
            const ulonglong2* kr = reinterpret_cast<const ulonglong2*>(&ksh[j][0]);
            ulonglong2 k0 = kr[0], k1 = kr[1];
            ull c0 = fma2(qp[0], k0.x, z2);
            ull c1 = fma2(qp[1], k0.y, z2);
            c0 = fma2(qp[2], k1.x, c0);
            c1 = fma2(qp[3], k1.y, c1);
            const ulonglong2* kr2 = reinterpret_cast<const ulonglong2*>(&ksh[j][2]);
            ulonglong2 k2 = kr2[0], k3 = kr2[1];
            c0 = fma2(qp[4], k2.x, c0);
            c1 = fma2(qp[5], k2.y, c1);
            c0 = fma2(qp[6], k3.x, c0);
            c1 = fma2(qp[7], k3.y, c1);
            float2 f0 = unpack2(c0), f1 = unpack2(c1);
            float sdot = (f0.x + f0.y) + (f1.x + f1.y);
            float p = __expf(sdot);
            l += p;
            ull pp = pack2(p, p);
            const ulonglong2* vr = reinterpret_cast<const ulonglong2*>(&vsh[j][0]);
            ulonglong2 v0 = vr[0], v1 = vr[1];
            oa[0] = fma2(pp, v0.x, oa[0]);
            oa[1] = fma2(pp, v0.y, oa[1]);
            oa[2] = fma2(pp, v1.x, oa[2]);
            oa[3] = fma2(pp, v1.y, oa[3]);
            const ulonglong2* vr2 = reinterpret_cast<const ulonglong2*>(&vsh[j][2]);
            ulonglong2 v2 = vr2[0], v3 = vr2[1];
            oa[4] = fma2(pp, v2.x, oa[4]);
            oa[5] = fma2(pp, v2.y, oa[5]);
            oa[6] = fma2(pp, v3.x, oa[6]);
            oa[7] = fma2(pp, v3.y, oa[7]);
        }
        float inv = 1.0f / l;
        float* orow = &O[(rowbase + tid) * EE + hq];
        #pragma unroll
        for (int c = 0; c < 4; c++) {
            float2 lo = unpack2(oa[c * 2 + 0]);
            float2 hi = unpack2(oa[c * 2 + 1]);
            float4 v = { lo.x * inv, lo.y * inv, hi.x * inv, hi.y * inv };
            *reinterpret_cast<float4*>(&orow[c * 4]) = v;
        }
    }
}

// ---------------- BatchNorm stats ----------------
#define BN_BLOCKS 808
#define ROWS_PER_BLK (TT / BN_BLOCKS)   // 64
__global__ __launch_bounds__(128) void bn_partial(const float* __restrict__ x,
                                                  float* __restrict__ psum,
                                                  float* __restrict__ psq)
{
    int e = threadIdx.x;
    int blk = blockIdx.x;
    int r0 = blk * ROWS_PER_BLK;
    float s = 0.f, s2 = 0.f;
    #pragma unroll 8
    for (int r = 0; r < ROWS_PER_BLK; r++) {
        float v = x[(size_t)(r0 + r) * EE + e];
        s += v; s2 += v * v;
    }
    psum[blk * EE + e] = s;
    psq [blk * EE + e] = s2;
}

__global__ __launch_bounds__(128) void bn_finalize(const float* __restrict__ psum,
                                                   const float* __restrict__ psq,
                                                   const float* __restrict__ g,
                                                   const float* __restrict__ be,
                                                   float* __restrict__ scale,
                                                   float* __restrict__ shift)
{
    int e = threadIdx.x;
    float s = 0.f, s2 = 0.f;
    #pragma unroll 8
    for (int i = 0; i < BN_BLOCKS; i++) { s += psum[i * EE + e]; s2 += psq[i * EE + e]; }
    float mu = s / (float)TT;
    float var = s2 / (float)TT - mu * mu;
    float sc = rsqrtf(var + EPS) * g[e];
    scale[e] = sc;
    shift[e] = be[e] - mu * sc;
}

__global__ __launch_bounds__(256) void bn_apply_final(const float* __restrict__ x,
                                                      const float* __restrict__ scale,
                                                      const float* __restrict__ shift,
                                                      float* __restrict__ y)
{
    int idx = blockIdx.x * 256 + threadIdx.x;
    if (idx >= TT * EE) return;
    int e = idx & (EE - 1);
    y[idx] = fmaf(x[idx], scale[e], shift[e]);
}

// ---------------- host orchestration ----------------
extern "C" void kernel_launch(void* const* d_in, const int* in_sizes, int n_in,
                              void* d_out, int out_size)
{
    const float* s    = (const float*)d_in[0];
    const int*   dd   = (const int*)  d_in[1];
    const float* e_w  = (const float*)d_in[2];
    const float* e_b  = (const float*)d_in[3];
    const float* ep_w = (const float*)d_in[4];
    const float* ep_b = (const float*)d_in[5];
    const float* Wq   = (const float*)d_in[6];
    const float* bq   = (const float*)d_in[7];
    const float* Wk   = (const float*)d_in[8];
    const float* bk   = (const float*)d_in[9];
    const float* Wv   = (const float*)d_in[10];
    const float* bv   = (const float*)d_in[11];
    const float* Wo   = (const float*)d_in[12];
    const float* bo   = (const float*)d_in[13];
    const float* Wf1  = (const float*)d_in[14];
    const float* bf1  = (const float*)d_in[15];
    const float* Wf2  = (const float*)d_in[16];
    const float* bf2  = (const float*)d_in[17];
    const float* g1   = (const float*)d_in[18];
    const float* be1  = (const float*)d_in[19];
    const float* g2   = (const float*)d_in[20];
    const float* be2  = (const float*)d_in[21];

    float *px, *pqkv, *po, *pt, *ph, *pwq, *pbq, *pps, *pps2, *pscale, *pshift;
    cudaGetSymbolAddress((void**)&px,     g_x);
    cudaGetSymbolAddress((void**)&pqkv,   g_qkv);
    cudaGetSymbolAddress((void**)&po,     g_o);
    cudaGetSymbolAddress((void**)&pt,     g_t);
    cudaGetSymbolAddress((void**)&ph,     g_h);
    cudaGetSymbolAddress((void**)&pwq,    g_wqkv);
    cudaGetSymbolAddress((void**)&pbq,    g_bqkv);
    cudaGetSymbolAddress((void**)&pps,    g_ps);
    cudaGetSymbolAddress((void**)&pps2,   g_ps2);
    cudaGetSymbolAddress((void**)&pscale, g_scale);
    cudaGetSymbolAddress((void**)&pshift, g_shift);

    static int smem_set = 0;
    if (!smem_set) {
        cudaFuncSetAttribute(gemm_ep, cudaFuncAttributeMaxDynamicSharedMemorySize, SM_GEMM);
        smem_set = 1;
    }

    const int elem_grid = (TT * EE) / 256;
    const dim3 gQKV(QKV / BNt, TT / BMt);   // (3, 202)
    const dim3 gE(EE / BNt, TT / BMt);      // (1, 202)
    const dim3 gF(FF / BNt, TT / BMt);      // (4, 202)

    embed_kernel<<<elem_grid, 256>>>(s, dd, e_w, e_b, ep_w, ep_b, px);
    pack_qkv<<<(3 * EE * QKV + 255) / 256, 256>>>(Wq, Wk, Wv, bq, bk, bv, pwq, pbq);

    const float* curS = nullptr;   // pending bn affine on current x (px)
    const float* curH = nullptr;

    for (int i = 0; i < 3; i++) {
        const float* Woi = Wo + (size_t)i * EE * EE;
        const float* W1i = Wf1 + (size_t)i * EE * FF;
        const float* W2i = Wf2 + (size_t)i * FF * EE;

        // qkv = bn(x) @ Wqkv + b
        gemm_ep<<<gQKV, 256, SM_GEMM>>>(px, pwq + (size_t)i * EE * QKV, pbq + i * QKV,
                                        nullptr, pqkv, EE, QKV, 0, curS, curH, nullptr, nullptr);
        attn_kernel<<<BB * MM, 128>>>(pqkv, po);

        // t1 = o @ Wo + bo + bn(x)
        gemm_ep<<<gE, 256, SM_GEMM>>>(po, Woi, bo + i * EE, px, pt, EE, EE, 1,
                                      nullptr, nullptr, curS, curH);
        bn_partial<<<BN_BLOCKS, 128>>>(pt, pps, pps2);
        bn_finalize<<<1, 128>>>(pps, pps2, g1 + i * EE, be1 + i * EE, pscale, pshift);

        // h = relu(bn1(t1) @ Wf1 + bf1)
        gemm_ep<<<gF, 256, SM_GEMM>>>(pt, W1i, bf1 + i * FF, nullptr, ph, EE, FF, 2,
                                      pscale, pshift, nullptr, nullptr);
        // t2 = h @ Wf2 + bf2 + bn1(t1)
        gemm_ep<<<gE, 256, SM_GEMM>>>(ph, W2i, bf2 + i * EE, pt, px, FF, EE, 1,
                                      nullptr, nullptr, pscale, pshift);
        bn_partial<<<BN_BLOCKS, 128>>>(px, pps, pps2);
        bn_finalize<<<1, 128>>>(pps, pps2, g2 + i * EE, be2 + i * EE, pscale, pshift);
        curS = pscale; curH = pshift;
    }
    bn_apply_final<<<elem_grid, 256>>>(px, pscale, pshift, (float*)d_out);
    (void)in_sizes; (void)n_in; (void)out_size;
}

// round 11
// speedup vs baseline: 1.9420x; 1.9420x over previous
#include <cuda_runtime.h>
#include <cuda_bf16.h>
#include <math.h>

// Problem constants
#define BB   512
#define NN   101
#define EE   128
#define MM   8
#define DKK  16
#define TT   (BB * NN)        // 51712 = 404 * 128
#define FF   (4 * EE)         // 512
#define QKV  (3 * EE)         // 384
#define EPS  1e-5f

typedef unsigned long long ull;

// ---------------- device scratch ----------------
__device__ float g_x[TT * EE];
__device__ float g_qkv[TT * QKV];
__device__ float g_o[TT * EE];
__device__ float g_t[TT * EE];
__device__ float g_h[TT * FF];
__device__ float g_wqkv[3 * EE * QKV];
__device__ float g_bqkv[3 * QKV];
__device__ float g_ps [808 * EE];
__device__ float g_ps2[808 * EE];
__device__ float g_scale[EE];
__device__ float g_shift[EE];

// ---------------- f32x2 helpers ----------------
__device__ __forceinline__ ull fma2(ull a, ull b, ull c)
{
    ull d;
    asm("fma.rn.f32x2 %0, %1, %2, %3;" : "=l"(d) : "l"(a), "l"(b), "l"(c));
    return d;
}
__device__ __forceinline__ ull pack2(float x, float y)
{
    ull r;
    asm("mov.b64 %0, {%1, %2};" : "=l"(r) : "f"(x), "f"(y));
    return r;
}
__device__ __forceinline__ float2 unpack2(ull v)
{
    float2 r;
    asm("mov.b64 {%0, %1}, %2;" : "=f"(r.x), "=f"(r.y) : "l"(v));
    return r;
}

// ---------------- embedding ----------------
__global__ void embed_kernel(const float* __restrict__ s, const int* __restrict__ d,
                             const float* __restrict__ e_w, const float* __restrict__ e_b,
                             const float* __restrict__ ep_w, const float* __restrict__ ep_b,
                             float* __restrict__ x)
{
    int idx = blockIdx.x * 256 + threadIdx.x;
    if (idx >= TT * EE) return;
    int e = idx & (EE - 1);
    int t = idx >> 7;
    int n = t % NN;
    int b = t / NN;
    float s0 = s[(b * NN + n) * 2 + 0];
    float s1 = s[(b * NN + n) * 2 + 1];
    float out;
    if (n == 0) {
        out = s0 * ep_w[e] + s1 * ep_w[EE + e] + ep_b[e];
    } else {
        float dd = (float)d[b * NN + n];
        out = s0 * e_w[e] + s1 * e_w[EE + e] + dd * e_w[2 * EE + e] + e_b[e];
    }
    x[idx] = out;
}

// ---------------- pack QKV weights ----------------
__global__ void pack_qkv(const float* __restrict__ Wq, const float* __restrict__ Wk,
                         const float* __restrict__ Wv, const float* __restrict__ bq,
                         const float* __restrict__ bk, const float* __restrict__ bv,
                         float* __restrict__ wout, float* __restrict__ bout)
{
    int idx = blockIdx.x * 256 + threadIdx.x;
    int total = 3 * EE * QKV;
    if (idx < total) {
        int i = idx / (EE * QKV);
        int r = idx % (EE * QKV);
        int k = r / QKV;
        int j = r % QKV;
        float v;
        if (j < EE)            v = Wq[(size_t)i * EE * EE + k * EE + j];
        else if (j < 2 * EE)   v = Wk[(size_t)i * EE * EE + k * EE + (j - EE)];
        else                   v = Wv[(size_t)i * EE * EE + k * EE + (j - 2 * EE)];
        wout[idx] = v;
    }
    if (idx < 3 * QKV) {
        int i = idx / QKV;
        int j = idx % QKV;
        float v;
        if (j < EE)            v = bq[i * EE + j];
        else if (j < 2 * EE)   v = bk[i * EE + (j - EE)];
        else                   v = bv[i * EE + (j - 2 * EE)];
        bout[idx] = v;
    }
}

// ---------------- GEMM v5: R7 128x128/8x8 core + register-staged prefetch --
// C = affA(A) @ W + bias [+ affR(res) | relu]
#define BMt 128
#define BKt 32
#define APAD 4
__global__ __launch_bounds__(256, 2) void gemm_ep(
    const float* __restrict__ A, const float* __restrict__ W,
    const float* __restrict__ bias, const float* __restrict__ res,
    float* __restrict__ C, int K, int Nout, int mode,
    const float* __restrict__ sA, const float* __restrict__ hA,
    const float* __restrict__ sR, const float* __restrict__ hR)
{
    const int t0 = blockIdx.y * BMt;
    const int n0 = blockIdx.x * BMt;
    __shared__ float As[BKt][BMt + APAD];   // transposed [k][m]
    __shared__ float Bs[BKt][BMt];          // [k][n]
    const int tid = threadIdx.x;
    const int tx = tid & 15;
    const int ty = tid >> 4;

    // per-thread load coordinates (fixed across tiles)
    const int a_row = tid >> 1;             // with p-offset: rows tid>>1 spread below
    ull acc[2][4][4];
    #pragma unroll
    for (int mq = 0; mq < 2; mq++)
        #pragma unroll
        for (int m = 0; m < 4; m++)
            #pragma unroll
            for (int p = 0; p < 4; p++)
                acc[mq][m][p] = pack2(0.f, 0.f);

    const int nk = K / BKt;

    // prologue: load tile 0 into registers
    float4 ra[4], rb[4];
    #pragma unroll
    for (int p = 0; p < 4; p++) {
        int i = p * 256 + tid;
        int row = i >> 3, c4 = i & 7;
        ra[p] = *reinterpret_cast<const float4*>(&A[(size_t)(t0 + row) * K + c4 * 4]);
    }
    #pragma unroll
    for (int p = 0; p < 4; p++) {
        int i = p * 256 + tid;
        int row = i >> 5, c4 = i & 31;
        rb[p] = *reinterpret_cast<const float4*>(&W[(size_t)row * Nout + n0 + c4 * 4]);
    }

    for (int it = 0; it < nk; ++it) {
        const int k0 = it * BKt;
        if (it) __syncthreads();            // previous compute done before smem overwrite

        // store staged tile into smem (A with optional affine, transposed)
        #pragma unroll
        for (int p = 0; p < 4; p++) {
            int i = p * 256 + tid;
            int row = i >> 3, c4 = i & 7;
            int kc = k0 + c4 * 4;
            float4 v = ra[p];
            if (sA) {
                float4 sc = *reinterpret_cast<const float4*>(&sA[kc]);
                float4 sh = *reinterpret_cast<const float4*>(&hA[kc]);
                v.x = fmaf(v.x, sc.x, sh.x);
                v.y = fmaf(v.y, sc.y, sh.y);
                v.z = fmaf(v.z, sc.z, sh.z);
                v.w = fmaf(v.w, sc.w, sh.w);
            }
            As[c4 * 4 + 0][row] = v.x;
            As[c4 * 4 + 1][row] = v.y;
            As[c4 * 4 + 2][row] = v.z;
            As[c4 * 4 + 3][row] = v.w;
        }
        #pragma unroll
        for (int p = 0; p < 4; p++) {
            int i = p * 256 + tid;
            int row = i >> 5, c4 = i & 31;
            *reinterpret_cast<float4*>(&Bs[row][c4 * 4]) = rb[p];
        }
        __syncthreads();

        // prefetch next tile into registers (overlaps with compute below)
        if (it + 1 < nk) {
            const int kn = k0 + BKt;
            #pragma unroll
            for (int p = 0; p < 4; p++) {
                int i = p * 256 + tid;
                int row = i >> 3, c4 = i & 7;
                ra[p] = *reinterpret_cast<const float4*>(&A[(size_t)(t0 + row) * K + kn + c4 * 4]);
            }
            #pragma unroll
            for (int p = 0; p < 4; p++) {
                int i = p * 256 + tid;
                int row = i >> 5, c4 = i & 31;
                rb[p] = *reinterpret_cast<const float4*>(&W[(size_t)(kn + row) * Nout + n0 + c4 * 4]);
            }
        }

        #pragma unroll 16
        for (int kk = 0; kk < BKt; kk++) {
            float4 a0 = *reinterpret_cast<const float4*>(&As[kk][ty * 4]);
            float4 a1 = *reinterpret_cast<const float4*>(&As[kk][64 + ty * 4]);
            ulonglong2 b0 = *reinterpret_cast<const ulonglong2*>(&Bs[kk][tx * 4]);
            ulonglong2 b1 = *reinterpret_cast<const ulonglong2*>(&Bs[kk][64 + tx * 4]);
            ull bp[4] = { b0.x, b0.y, b1.x, b1.y };
            ull ap[8];
            ap[0] = pack2(a0.x, a0.x); ap[1] = pack2(a0.y, a0.y);
            ap[2] = pack2(a0.z, a0.z); ap[3] = pack2(a0.w, a0.w);
            ap[4] = pack2(a1.x, a1.x); ap[5] = pack2(a1.y, a1.y);
            ap[6] = pack2(a1.z, a1.z); ap[7] = pack2(a1.w, a1.w);
            #pragma unroll
            for (int mq = 0; mq < 2; mq++)
                #pragma unroll
                for (int m = 0; m < 4; m++)
                    #pragma unroll
                    for (int p = 0; p < 4; p++)
                        acc[mq][m][p] = fma2(ap[mq * 4 + m], bp[p], acc[mq][m][p]);
        }
    }
    __syncthreads();

    // epilogue
    #pragma unroll
    for (int cq = 0; cq < 2; cq++) {
        int col = n0 + cq * 64 + tx * 4;
        float4 b4 = *reinterpret_cast<const float4*>(&bias[col]);
        float4 sR4 = {1.f,1.f,1.f,1.f}, hR4 = {0.f,0.f,0.f,0.f};
        if (mode == 1 && sR) {
            sR4 = *reinterpret_cast<const float4*>(&sR[col]);
            hR4 = *reinterpret_cast<const float4*>(&hR[col]);
        }
        #pragma unroll
        for (int mq = 0; mq < 2; mq++) {
            #pragma unroll
            for (int m = 0; m < 4; m++) {
                int row = t0 + mq * 64 + ty * 4 + m;
                float2 lo = unpack2(acc[mq][m][cq * 2 + 0]);
                float2 hi = unpack2(acc[mq][m][cq * 2 + 1]);
                float4 v = { lo.x + b4.x, lo.y + b4.y, hi.x + b4.z, hi.y + b4.w };
                if (mode == 1) {
                    float4 r4 = *reinterpret_cast<const float4*>(&res[(size_t)row * Nout + col]);
                    v.x += fmaf(r4.x, sR4.x, hR4.x);
                    v.y += fmaf(r4.y, sR4.y, hR4.y);
                    v.z += fmaf(r4.z, sR4.z, hR4.z);
                    v.w += fmaf(r4.w, sR4.w, hR4.w);
                } else if (mode == 2) {
                    v.x = fmaxf(v.x, 0.f); v.y = fmaxf(v.y, 0.f);
                    v.z = fmaxf(v.z, 0.f); v.w = fmaxf(v.w, 0.f);
                }
                *reinterpret_cast<float4*>(&C[(size_t)row * Nout + col]) = v;
            }
        }
    }
}

// ---------------- attention v2 (R7-measured): single-pass f32x2 ------------
__global__ __launch_bounds__(128) void attn_kernel(
    const float* __restrict__ QKVb, float* __restrict__ O)
{
    int bh = blockIdx.x;
    int b = bh >> 3;
    int h = bh & 7;
    const size_t rowbase = (size_t)b * NN;
    const int hq = h * DKK;

    __shared__ float4 ksh[NN][4];
    __shared__ float4 vsh[NN][4];
    int tid = threadIdx.x;
    for (int i = tid; i < NN * 4; i += 128) {
        int j = i >> 2, c = i & 3;
        ksh[j][c] = *reinterpret_cast<const float4*>(&QKVb[(rowbase + j) * QKV + EE     + hq + c * 4]);
        vsh[j][c] = *reinterpret_cast<const float4*>(&QKVb[(rowbase + j) * QKV + 2 * EE + hq + c * 4]);
    }
    __syncthreads();

    if (tid < NN) {
        ull qp[8];
        #pragma unroll
        for (int c = 0; c < 4; c++) {
            float4 q4 = *reinterpret_cast<const float4*>(&QKVb[(rowbase + tid) * QKV + hq + c * 4]);
            qp[c * 2 + 0] = pack2(q4.x * 0.25f, q4.y * 0.25f);
            qp[c * 2 + 1] = pack2(q4.z * 0.25f, q4.w * 0.25f);
        }
        const ull z2 = pack2(0.f, 0.f);
        ull oa[8];
        #pragma unroll
        for (int c = 0; c < 8; c++) oa[c] = z2;
        float l = 0.f;

        for (int j = 0; j < NN; j++) {
            const ulonglong2* kr = reinterpret_cast<const ulonglong2*>(&ksh[j][0]);
            ulonglong2 k0 = kr[0], k1 = kr[1];
            ull c0 = fma2(qp[0], k0.x, z2);
            ull c1 = fma2(qp[1], k0.y, z2);
            c0 = fma2(qp[2], k1.x, c0);
            c1 = fma2(qp[3], k1.y, c1);
            const ulonglong2* kr2 = reinterpret_cast<const ulonglong2*>(&ksh[j][2]);
            ulonglong2 k2 = kr2[0], k3 = kr2[1];
            c0 = fma2(qp[4], k2.x, c0);
            c1 = fma2(qp[5], k2.y, c1);
            c0 = fma2(qp[6], k3.x, c0);
            c1 = fma2(qp[7], k3.y, c1);
            float2 f0 = unpack2(c0), f1 = unpack2(c1);
            float sdot = (f0.x + f0.y) + (f1.x + f1.y);
            float p = __expf(sdot);
            l += p;
            ull pp = pack2(p, p);
            const ulonglong2* vr = reinterpret_cast<const ulonglong2*>(&vsh[j][0]);
            ulonglong2 v0 = vr[0], v1 = vr[1];
            oa[0] = fma2(pp, v0.x, oa[0]);
            oa[1] = fma2(pp, v0.y, oa[1]);
            oa[2] = fma2(pp, v1.x, oa[2]);
            oa[3] = fma2(pp, v1.y, oa[3]);
            const ulonglong2* vr2 = reinterpret_cast<const ulonglong2*>(&vsh[j][2]);
            ulonglong2 v2 = vr2[0], v3 = vr2[1];
            oa[4] = fma2(pp, v2.x, oa[4]);
            oa[5] = fma2(pp, v2.y, oa[5]);
            oa[6] = fma2(pp, v3.x, oa[6]);
            oa[7] = fma2(pp, v3.y, oa[7]);
        }
        float inv = 1.0f / l;
        float* orow = &O[(rowbase + tid) * EE + hq];
        #pragma unroll
        for (int c = 0; c < 4; c++) {
            float2 lo = unpack2(oa[c * 2 + 0]);
            float2 hi = unpack2(oa[c * 2 + 1]);
            float4 v = { lo.x * inv, lo.y * inv, hi.x * inv, hi.y * inv };
            *reinterpret_cast<float4*>(&orow[c * 4]) = v;
        }
    }
}

// ---------------- BatchNorm stats ----------------
#define BN_BLOCKS 808
#define ROWS_PER_BLK (TT / BN_BLOCKS)   // 64
__global__ __launch_bounds__(128) void bn_partial(const float* __restrict__ x,
                                                  float* __restrict__ psum,
                                                  float* __restrict__ psq)
{
    int e = threadIdx.x;
    int blk = blockIdx.x;
    int r0 = blk * ROWS_PER_BLK;
    float s = 0.f, s2 = 0.f;
    #pragma unroll 8
    for (int r = 0; r < ROWS_PER_BLK; r++) {
        float v = x[(size_t)(r0 + r) * EE + e];
        s += v; s2 += v * v;
    }
    psum[blk * EE + e] = s;
    psq [blk * EE + e] = s2;
}

__global__ __launch_bounds__(128) void bn_finalize(const float* __restrict__ psum,
                                                   const float* __restrict__ psq,
                                                   const float* __restrict__ g,
                                                   const float* __restrict__ be,
                                                   float* __restrict__ scale,
                                                   float* __restrict__ shift)
{
    int e = threadIdx.x;
    float s = 0.f, s2 = 0.f;
    #pragma unroll 8
    for (int i = 0; i < BN_BLOCKS; i++) { s += psum[i * EE + e]; s2 += psq[i * EE + e]; }
    float mu = s / (float)TT;
    float var = s2 / (float)TT - mu * mu;
    float sc = rsqrtf(var + EPS) * g[e];
    scale[e] = sc;
    shift[e] = be[e] - mu * sc;
}

__global__ __launch_bounds__(256) void bn_apply_final(const float* __restrict__ x,
                                                      const float* __restrict__ scale,
                                                      const float* __restrict__ shift,
                                                      float* __restrict__ y)
{
    int idx = blockIdx.x * 256 + threadIdx.x;
    if (idx >= TT * EE) return;
    int e = idx & (EE - 1);
    y[idx] = fmaf(x[idx], scale[e], shift[e]);
}

// ---------------- host orchestration ----------------
extern "C" void kernel_launch(void* const* d_in, const int* in_sizes, int n_in,
                              void* d_out, int out_size)
{
    const float* s    = (const float*)d_in[0];
    const int*   dd   = (const int*)  d_in[1];
    const float* e_w  = (const float*)d_in[2];
    const float* e_b  = (const float*)d_in[3];
    const float* ep_w = (const float*)d_in[4];
    const float* ep_b = (const float*)d_in[5];
    const float* Wq   = (const float*)d_in[6];
    const float* bq   = (const float*)d_in[7];
    const float* Wk   = (const float*)d_in[8];
    const float* bk   = (const float*)d_in[9];
    const float* Wv   = (const float*)d_in[10];
    const float* bv   = (const float*)d_in[11];
    const float* Wo   = (const float*)d_in[12];
    const float* bo   = (const float*)d_in[13];
    const float* Wf1  = (const float*)d_in[14];
    const float* bf1  = (const float*)d_in[15];
    const float* Wf2  = (const float*)d_in[16];
    const float* bf2  = (const float*)d_in[17];
    const float* g1   = (const float*)d_in[18];
    const float* be1  = (const float*)d_in[19];
    const float* g2   = (const float*)d_in[20];
    const float* be2  = (const float*)d_in[21];

    float *px, *pqkv, *po, *pt, *ph, *pwq, *pbq, *pps, *pps2, *pscale, *pshift;
    cudaGetSymbolAddress((void**)&px,     g_x);
    cudaGetSymbolAddress((void**)&pqkv,   g_qkv);
    cudaGetSymbolAddress((void**)&po,     g_o);
    cudaGetSymbolAddress((void**)&pt,     g_t);
    cudaGetSymbolAddress((void**)&ph,     g_h);
    cudaGetSymbolAddress((void**)&pwq,    g_wqkv);
    cudaGetSymbolAddress((void**)&pbq,    g_bqkv);
    cudaGetSymbolAddress((void**)&pps,    g_ps);
    cudaGetSymbolAddress((void**)&pps2,   g_ps2);
    cudaGetSymbolAddress((void**)&pscale, g_scale);
    cudaGetSymbolAddress((void**)&pshift, g_shift);

    const int elem_grid = (TT * EE) / 256;
    const dim3 gQKV(QKV / BMt, TT / BMt);   // (3, 404)
    const dim3 gE(EE / BMt, TT / BMt);      // (1, 404)
    const dim3 gF(FF / BMt, TT / BMt);      // (4, 404)

    embed_kernel<<<elem_grid, 256>>>(s, dd, e_w, e_b, ep_w, ep_b, px);
    pack_qkv<<<(3 * EE * QKV + 255) / 256, 256>>>(Wq, Wk, Wv, bq, bk, bv, pwq, pbq);

    const float* curS = nullptr;   // pending bn affine on current x (px)
    const float* curH = nullptr;

    for (int i = 0; i < 3; i++) {
        const float* Woi = Wo + (size_t)i * EE * EE;
        const float* W1i = Wf1 + (size_t)i * EE * FF;
        const float* W2i = Wf2 + (size_t)i * FF * EE;

        // qkv = bn(x) @ Wqkv + b
        gemm_ep<<<gQKV, 256>>>(px, pwq + (size_t)i * EE * QKV, pbq + i * QKV,
                               nullptr, pqkv, EE, QKV, 0, curS, curH, nullptr, nullptr);
        attn_kernel<<<BB * MM, 128>>>(pqkv, po);

        // t1 = o @ Wo + bo + bn(x)
        gemm_ep<<<gE, 256>>>(po, Woi, bo + i * EE, px, pt, EE, EE, 1,
                             nullptr, nullptr, curS, curH);
        bn_partial<<<BN_BLOCKS, 128>>>(pt, pps, pps2);
        bn_finalize<<<1, 128>>>(pps, pps2, g1 + i * EE, be1 + i * EE, pscale, pshift);

        // h = relu(bn1(t1) @ Wf1 + bf1)
        gemm_ep<<<gF, 256>>>(pt, W1i, bf1 + i * FF, nullptr, ph, EE, FF, 2,
                             pscale, pshift, nullptr, nullptr);
        // t2 = h @ Wf2 + bf2 + bn1(t1)
        gemm_ep<<<gE, 256>>>(ph, W2i, bf2 + i * EE, pt, px, FF, EE, 1,
                             nullptr, nullptr, pscale, pshift);
        bn_partial<<<BN_BLOCKS, 128>>>(px, pps, pps2);
        bn_finalize<<<1, 128>>>(pps, pps2, g2 + i * EE, be2 + i * EE, pscale, pshift);
        curS = pscale; curH = pshift;
    }
    bn_apply_final<<<elem_grid, 256>>>(px, pscale, pshift, (float*)d_out);
    (void)in_sizes; (void)n_in; (void)out_size;
}

// round 13
// speedup vs baseline: 2.3963x; 1.2339x over previous
#include <cuda_runtime.h>
#include <cuda_bf16.h>
#include <math.h>
#include <cstdint>

// Problem constants
#define BB   512
#define NN   101
#define EE   128
#define MM   8
#define DKK  16
#define TT   (BB * NN)        // 51712 = 404 * 128
#define FF   (4 * EE)         // 512
#define QKV  (3 * EE)         // 384
#define EPS  1e-5f

typedef unsigned long long ull;

// ---------------- device scratch ----------------
__device__ float g_x[TT * EE];
__device__ float g_qkv[TT * QKV];
__device__ float g_o[TT * EE];
__device__ float g_t[TT * EE];
__device__ float g_h[TT * FF];
__device__ float g_bqkv[3 * QKV];
__device__ __nv_bfloat16 g_wth[3 * 196608];   // split-hi weights, [K][N] layout per region
__device__ __nv_bfloat16 g_wtl[3 * 196608];   // split-lo
__device__ float g_ps [256 * EE];
__device__ float g_ps2[256 * EE];
__device__ float g_scale[EE];
__device__ float g_shift[EE];

// ---------------- helpers ----------------
__device__ __forceinline__ ull fma2(ull a, ull b, ull c)
{
    ull d;
    asm("fma.rn.f32x2 %0, %1, %2, %3;" : "=l"(d) : "l"(a), "l"(b), "l"(c));
    return d;
}
__device__ __forceinline__ ull pack2(float x, float y)
{
    ull r;
    asm("mov.b64 %0, {%1, %2};" : "=l"(r) : "f"(x), "f"(y));
    return r;
}
__device__ __forceinline__ float2 unpack2(ull v)
{
    float2 r;
    asm("mov.b64 {%0, %1}, %2;" : "=f"(r.x), "=f"(r.y) : "l"(v));
    return r;
}
__device__ __forceinline__ uint32_t smem_u32(const void* p)
{
    return (uint32_t)__cvta_generic_to_shared(p);
}
__device__ __forceinline__ uint32_t bf2u(__nv_bfloat16 a, __nv_bfloat16 b)
{
    return ((uint32_t)__bfloat16_as_ushort(b) << 16) | __bfloat16_as_ushort(a);
}

__device__ __forceinline__ void ldsm_x4(uint32_t* r, uint32_t addr)
{
    asm volatile("ldmatrix.sync.aligned.m8n8.x4.shared.b16 {%0,%1,%2,%3}, [%4];"
                 : "=r"(r[0]), "=r"(r[1]), "=r"(r[2]), "=r"(r[3]) : "r"(addr));
}
__device__ __forceinline__ void ldsm_x4t(uint32_t* r, uint32_t addr)
{
    asm volatile("ldmatrix.sync.aligned.m8n8.x4.trans.shared.b16 {%0,%1,%2,%3}, [%4];"
                 : "=r"(r[0]), "=r"(r[1]), "=r"(r[2]), "=r"(r[3]) : "r"(addr));
}
__device__ __forceinline__ void mma16816(float* c, const uint32_t* a,
                                         uint32_t b0, uint32_t b1)
{
    asm volatile(
        "mma.sync.aligned.m16n8k16.row.col.f32.bf16.bf16.f32 "
        "{%0,%1,%2,%3}, {%4,%5,%6,%7}, {%8,%9}, {%0,%1,%2,%3};"
        : "+f"(c[0]), "+f"(c[1]), "+f"(c[2]), "+f"(c[3])
        : "r"(a[0]), "r"(a[1]), "r"(a[2]), "r"(a[3]), "r"(b0), "r"(b1));
}

// ---------------- embedding ----------------
__global__ void embed_kernel(const float* __restrict__ s, const int* __restrict__ d,
                             const float* __restrict__ e_w, const float* __restrict__ e_b,
                             const float* __restrict__ ep_w, const float* __restrict__ ep_b,
                             float* __restrict__ x)
{
    int idx = blockIdx.x * 256 + threadIdx.x;
    if (idx >= TT * EE) return;
    int e = idx & (EE - 1);
    int t = idx >> 7;
    int n = t % NN;
    int b = t / NN;
    float s0 = s[(b * NN + n) * 2 + 0];
    float s1 = s[(b * NN + n) * 2 + 1];
    float out;
    if (n == 0) {
        out = s0 * ep_w[e] + s1 * ep_w[EE + e] + ep_b[e];
    } else {
        float dd = (float)d[b * NN + n];
        out = s0 * e_w[e] + s1 * e_w[EE + e] + dd * e_w[2 * EE + e] + e_b[e];
    }
    x[idx] = out;
}

// ---------------- pack: split all weights (keep [K][N] orientation) --------
// per-layer element offsets: qkv@0 (128x384 fused), wo@49152 (128x128),
// wf1@65536 (128x512), wf2@131072 (512x128); layer stride 196608
__global__ void pack_all(const float* __restrict__ Wq, const float* __restrict__ Wk,
                         const float* __restrict__ Wv, const float* __restrict__ Wo,
                         const float* __restrict__ Wf1, const float* __restrict__ Wf2,
                         __nv_bfloat16* __restrict__ hi, __nv_bfloat16* __restrict__ lo)
{
    int idx = blockIdx.x * 256 + threadIdx.x;
    if (idx >= 3 * 196608) return;
    int layer = idx / 196608;
    int r = idx % 196608;
    float v;
    if (r < 49152) {
        int k = r / 384, j = r % 384;
        int sel = j >> 7, n = j & 127;
        const float* W = (sel == 0) ? Wq : (sel == 1) ? Wk : Wv;
        v = W[layer * 16384 + k * 128 + n];
    } else if (r < 65536) {
        v = Wo[layer * 16384 + (r - 49152)];
    } else if (r < 131072) {
        v = Wf1[layer * 65536 + (r - 65536)];
    } else {
        v = Wf2[layer * 65536 + (r - 131072)];
    }
    __nv_bfloat16 h = __float2bfloat16(v);
    __nv_bfloat16 l = __float2bfloat16(v - __bfloat162float(h));
    hi[idx] = h;
    lo[idx] = l;
}

__global__ void pack_bias(const float* __restrict__ bq, const float* __restrict__ bk,
                          const float* __restrict__ bv, float* __restrict__ bout)
{
    int idx = blockIdx.x * 256 + threadIdx.x;
    if (idx >= 3 * QKV) return;
    int i = idx / QKV;
    int j = idx % QKV;
    float v;
    if (j < EE)          v = bq[i * EE + j];
    else if (j < 2 * EE) v = bk[i * EE + (j - EE)];
    else                 v = bv[i * EE + (j - 2 * EE)];
    bout[idx] = v;
}

// ---------------- tensor-core GEMM (mma.sync, split-bf16) ----------------
// C[128t x 128n] = affA(A) @ W + bias [+ affR(res) | relu]
// W given as split hi/lo bf16 in [K][Nout] layout.
#define AST 40     // A smem row stride (bf16 elems) = 80B, conflict-free LDSM
#define BST 136    // B smem row stride (bf16 elems) = 272B, conflict-free LDSM

__global__ __launch_bounds__(256) void gemm_mma(
    const float* __restrict__ A,
    const __nv_bfloat16* __restrict__ Whi, const __nv_bfloat16* __restrict__ Wlo,
    const float* __restrict__ bias, const float* __restrict__ res,
    float* __restrict__ C, int K, int Nout, int mode,
    const float* __restrict__ sA, const float* __restrict__ hA,
    const float* __restrict__ sR, const float* __restrict__ hR)
{
    __shared__ __nv_bfloat16 sAh[128 * AST];
    __shared__ __nv_bfloat16 sAl[128 * AST];
    __shared__ __nv_bfloat16 sBh[32 * BST];
    __shared__ __nv_bfloat16 sBl[32 * BST];

    const int tid  = threadIdx.x;
    const int lane = tid & 31;
    const int wid  = tid >> 5;
    const int warp_m = wid >> 1;          // 0..3
    const int warp_n = wid & 1;           // 0..1
    const int m0 = warp_m * 32;
    const int nb0 = warp_n * 64;
    const int t0 = blockIdx.y * 128;
    const int nblk = blockIdx.x * 128;

    // loader coords
    const int arow  = tid >> 1;           // 0..127
    const int akoff = (tid & 1) * 16;     // 0 or 16
    const int bkrow = tid >> 3;           // 0..31
    const int bnoff = (tid & 7) * 16;     // 0..112

    float acc[2][8][4];
    #pragma unroll
    for (int mi = 0; mi < 2; mi++)
        #pragma unroll
        for (int ni = 0; ni < 8; ni++)
            #pragma unroll
            for (int q = 0; q < 4; q++)
                acc[mi][ni][q] = 0.f;

    const uint32_t sAh_u = smem_u32(sAh);
    const uint32_t sAl_u = smem_u32(sAl);
    const uint32_t sBh_u = smem_u32(sBh);
    const uint32_t sBl_u = smem_u32(sBl);

    const int nCh = K >> 5;
    for (int ch = 0; ch < nCh; ch++) {
        const int k0 = ch << 5;
        if (ch) __syncthreads();

        // ---- A stage: fp32 -> affine -> split hi/lo bf16
        {
            const float* ap = A + (size_t)(t0 + arow) * K + k0 + akoff;
            float vv[16];
            #pragma unroll
            for (int q = 0; q < 4; q++) {
                float4 v = *reinterpret_cast<const float4*>(ap + q * 4);
                vv[q*4+0] = v.x; vv[q*4+1] = v.y; vv[q*4+2] = v.z; vv[q*4+3] = v.w;
            }
            if (sA) {
                #pragma unroll
                for (int q = 0; q < 16; q++) {
                    int kc = k0 + akoff + q;
                    vv[q] = fmaf(vv[q], sA[kc], hA[kc]);
                }
            }
            uint32_t H[8], L[8];
            #pragma unroll
            for (int q = 0; q < 8; q++) {
                __nv_bfloat16 h0 = __float2bfloat16(vv[q*2+0]);
                __nv_bfloat16 h1 = __float2bfloat16(vv[q*2+1]);
                __nv_bfloat16 l0 = __float2bfloat16(vv[q*2+0] - __bfloat162float(h0));
                __nv_bfloat16 l1 = __float2bfloat16(vv[q*2+1] - __bfloat162float(h1));
                H[q] = bf2u(h0, h1);
                L[q] = bf2u(l0, l1);
            }
            uint4* dh = reinterpret_cast<uint4*>(sAh + arow * AST + akoff);
            uint4* dl = reinterpret_cast<uint4*>(sAl + arow * AST + akoff);
            dh[0] = make_uint4(H[0], H[1], H[2], H[3]);
            dh[1] = make_uint4(H[4], H[5], H[6], H[7]);
            dl[0] = make_uint4(L[0], L[1], L[2], L[3]);
            dl[1] = make_uint4(L[4], L[5], L[6], L[7]);
        }
        // ---- B stage: bf16 [k][n] direct copy (coalesced)
        {
            const uint4* bh = reinterpret_cast<const uint4*>(Whi + (size_t)(k0 + bkrow) * Nout + nblk + bnoff);
            const uint4* bl = reinterpret_cast<const uint4*>(Wlo + (size_t)(k0 + bkrow) * Nout + nblk + bnoff);
            uint4* dh = reinterpret_cast<uint4*>(sBh + bkrow * BST + bnoff);
            uint4* dl = reinterpret_cast<uint4*>(sBl + bkrow * BST + bnoff);
            dh[0] = bh[0]; dh[1] = bh[1];
            dl[0] = bl[0]; dl[1] = bl[1];
        }
        __syncthreads();

        // ---- compute: two k16 steps
        #pragma unroll
        for (int ks = 0; ks < 32; ks += 16) {
            uint32_t ah[2][4], al[2][4];
            #pragma unroll
            for (int mi = 0; mi < 2; mi++) {
                uint32_t aoff = (uint32_t)((m0 + mi * 16 + (lane & 15)) * AST
                                           + ks + ((lane >> 4) & 1) * 8) * 2;
                ldsm_x4(ah[mi], sAh_u + aoff);
                ldsm_x4(al[mi], sAl_u + aoff);
            }
            #pragma unroll
            for (int nt = 0; nt < 4; nt++) {
                uint32_t boff = (uint32_t)((ks + (lane & 15)) * BST
                                           + nb0 + nt * 16 + ((lane >> 4) & 1) * 8) * 2;
                uint32_t bh[4], bl[4];
                ldsm_x4t(bh, sBh_u + boff);
                ldsm_x4t(bl, sBl_u + boff);
                #pragma unroll
                for (int mi = 0; mi < 2; mi++) {
                    mma16816(acc[mi][nt*2+0], ah[mi], bh[0], bh[1]);
                    mma16816(acc[mi][nt*2+1], ah[mi], bh[2], bh[3]);
                    mma16816(acc[mi][nt*2+0], ah[mi], bl[0], bl[1]);
                    mma16816(acc[mi][nt*2+1], ah[mi], bl[2], bl[3]);
                    mma16816(acc[mi][nt*2+0], al[mi], bh[0], bh[1]);
                    mma16816(acc[mi][nt*2+1], al[mi], bh[2], bh[3]);
                }
            }
        }
    }

    // ---- epilogue: fragment rows l/4 & l/4+8, cols (l%4)*2,+1
    const int rql = lane >> 2;          // 0..7
    const int cql = (lane & 3) * 2;
    #pragma unroll
    for (int mi = 0; mi < 2; mi++) {
        #pragma unroll
        for (int ni = 0; ni < 8; ni++) {
            int c = nblk + nb0 + ni * 8 + cql;
            float2 b2 = *reinterpret_cast<const float2*>(&bias[c]);
            float2 sr2 = {1.f, 1.f}, hr2 = {0.f, 0.f};
            if (mode == 1 && sR) {
                sr2 = *reinterpret_cast<const float2*>(&sR[c]);
                hr2 = *reinterpret_cast<const float2*>(&hR[c]);
            }
            #pragma unroll
            for (int half = 0; half < 2; half++) {
                int r = t0 + m0 + mi * 16 + rql + half * 8;
                float v0 = acc[mi][ni][half * 2 + 0] + b2.x;
                float v1 = acc[mi][ni][half * 2 + 1] + b2.y;
                if (mode == 1) {
                    float2 r2 = *reinterpret_cast<const float2*>(&res[(size_t)r * Nout + c]);
                    if (sR) {
                        v0 += fmaf(r2.x, sr2.x, hr2.x);
                        v1 += fmaf(r2.y, sr2.y, hr2.y);
                    } else {
                        v0 += r2.x; v1 += r2.y;
                    }
                } else if (mode == 2) {
                    v0 = fmaxf(v0, 0.f);
                    v1 = fmaxf(v1, 0.f);
                }
                float2 out = {v0, v1};
                *reinterpret_cast<float2*>(&C[(size_t)r * Nout + c]) = out;
            }
        }
    }
}

// ---------------- attention v2 (R7-measured): single-pass f32x2 ------------
__global__ __launch_bounds__(128) void attn_kernel(
    const float* __restrict__ QKVb, float* __restrict__ O)
{
    int bh = blockIdx.x;
    int b = bh >> 3;
    int h = bh & 7;
    const size_t rowbase = (size_t)b * NN;
    const int hq = h * DKK;

    __shared__ float4 ksh[NN][4];
    __shared__ float4 vsh[NN][4];
    int tid = threadIdx.x;
    for (int i = tid; i < NN * 4; i += 128) {
        int j = i >> 2, c = i & 3;
        ksh[j][c] = *reinterpret_cast<const float4*>(&QKVb[(rowbase + j) * QKV + EE     + hq + c * 4]);
        vsh[j][c] = *reinterpret_cast<const float4*>(&QKVb[(rowbase + j) * QKV + 2 * EE + hq + c * 4]);
    }
    __syncthreads();

    if (tid < NN) {
        ull qp[8];
        #pragma unroll
        for (int c = 0; c < 4; c++) {
            float4 q4 = *reinterpret_cast<const float4*>(&QKVb[(rowbase + tid) * QKV + hq + c * 4]);
            qp[c * 2 + 0] = pack2(q4.x * 0.25f, q4.y * 0.25f);
            qp[c * 2 + 1] = pack2(q4.z * 0.25f, q4.w * 0.25f);
        }
        const ull z2 = pack2(0.f, 0.f);
        ull oa[8];
        #pragma unroll
        for (int c = 0; c < 8; c++) oa[c] = z2;
        float l = 0.f;

        for (int j = 0; j < NN; j++) {
            const ulonglong2* kr = reinterpret_cast<const ulonglong2*>(&ksh[j][0]);
            ulonglong2 k0 = kr[0], k1 = kr[1];
            ull c0 = fma2(qp[0], k0.x, z2);
            ull c1 = fma2(qp[1], k0.y, z2);
            c0 = fma2(qp[2], k1.x, c0);
            c1 = fma2(qp[3], k1.y, c1);
            const ulonglong2* kr2 = reinterpret_cast<const ulonglong2*>(&ksh[j][2]);
            ulonglong2 k2 = kr2[0], k3 = kr2[1];
            c0 = fma2(qp[4], k2.x, c0);
            c1 = fma2(qp[5], k2.y, c1);
            c0 = fma2(qp[6], k3.x, c0);
            c1 = fma2(qp[7], k3.y, c1);
            float2 f0 = unpack2(c0), f1 = unpack2(c1);
            float sdot = (f0.x + f0.y) + (f1.x + f1.y);
            float p = __expf(sdot);
            l += p;
            ull pp = pack2(p, p);
            const ulonglong2* vr = reinterpret_cast<const ulonglong2*>(&vsh[j][0]);
            ulonglong2 v0 = vr[0], v1 = vr[1];
            oa[0] = fma2(pp, v0.x, oa[0]);
            oa[1] = fma2(pp, v0.y, oa[1]);
            oa[2] = fma2(pp, v1.x, oa[2]);
            oa[3] = fma2(pp, v1.y, oa[3]);
            const ulonglong2* vr2 = reinterpret_cast<const ulonglong2*>(&vsh[j][2]);
            ulonglong2 v2 = vr2[0], v3 = vr2[1];
            oa[4] = fma2(pp, v2.x, oa[4]);
            oa[5] = fma2(pp, v2.y, oa[5]);
            oa[6] = fma2(pp, v3.x, oa[6]);
            oa[7] = fma2(pp, v3.y, oa[7]);
        }
        float inv = 1.0f / l;
        float* orow = &O[(rowbase + tid) * EE + hq];
        #pragma unroll
        for (int c = 0; c < 4; c++) {
            float2 lo = unpack2(oa[c * 2 + 0]);
            float2 hi = unpack2(oa[c * 2 + 1]);
            float4 v = { lo.x * inv, lo.y * inv, hi.x * inv, hi.y * inv };
            *reinterpret_cast<float4*>(&orow[c * 4]) = v;
        }
    }
}

// ---------------- BatchNorm stats (R7-measured) ----------------
#define BN_BLOCKS 256
#define ROWS_PER_BLK (TT / BN_BLOCKS)   // 202
__global__ __launch_bounds__(128) void bn_partial(const float* __restrict__ x,
                                                  float* __restrict__ psum,
                                                  float* __restrict__ psq)
{
    int e = threadIdx.x;
    int blk = blockIdx.x;
    int r0 = blk * ROWS_PER_BLK;
    float s = 0.f, s2 = 0.f;
    #pragma unroll 4
    for (int r = 0; r < ROWS_PER_BLK; r++) {
        float v = x[(size_t)(r0 + r) * EE + e];
        s += v; s2 += v * v;
    }
    psum[blk * EE + e] = s;
    psq [blk * EE + e] = s2;
}

__global__ __launch_bounds__(128) void bn_finalize(const float* __restrict__ psum,
                                                   const float* __restrict__ psq,
                                                   const float* __restrict__ g,
                                                   const float* __restrict__ be,
                                                   float* __restrict__ scale,
                                                   float* __restrict__ shift)
{
    int e = threadIdx.x;
    float s = 0.f, s2 = 0.f;
    #pragma unroll 8
    for (int i = 0; i < BN_BLOCKS; i++) { s += psum[i * EE + e]; s2 += psq[i * EE + e]; }
    float mu = s / (float)TT;
    float var = s2 / (float)TT - mu * mu;
    float sc = rsqrtf(var + EPS) * g[e];
    scale[e] = sc;
    shift[e] = be[e] - mu * sc;
}

__global__ __launch_bounds__(256) void bn_apply_final(const float* __restrict__ x,
                                                      const float* __restrict__ scale,
                                                      const float* __restrict__ shift,
                                                      float* __restrict__ y)
{
    int idx = blockIdx.x * 256 + threadIdx.x;
    if (idx >= TT * EE) return;
    int e = idx & (EE - 1);
    y[idx] = fmaf(x[idx], scale[e], shift[e]);
}

// ---------------- host orchestration ----------------
extern "C" void kernel_launch(void* const* d_in, const int* in_sizes, int n_in,
                              void* d_out, int out_size)
{
    const float* s    = (const float*)d_in[0];
    const int*   dd   = (const int*)  d_in[1];
    const float* e_w  = (const float*)d_in[2];
    const float* e_b  = (const float*)d_in[3];
    const float* ep_w = (const float*)d_in[4];
    const float* ep_b = (const float*)d_in[5];
    const float* Wq   = (const float*)d_in[6];
    const float* bq   = (const float*)d_in[7];
    const float* Wk   = (const float*)d_in[8];
    const float* bk   = (const float*)d_in[9];
    const float* Wv   = (const float*)d_in[10];
    const float* bv   = (const float*)d_in[11];
    const float* Wo   = (const float*)d_in[12];
    const float* bo   = (const float*)d_in[13];
    const float* Wf1  = (const float*)d_in[14];
    const float* bf1  = (const float*)d_in[15];
    const float* Wf2  = (const float*)d_in[16];
    const float* bf2  = (const float*)d_in[17];
    const float* g1   = (const float*)d_in[18];
    const float* be1  = (const float*)d_in[19];
    const float* g2   = (const float*)d_in[20];
    const float* be2  = (const float*)d_in[21];

    float *px, *pqkv, *po, *pt, *ph, *pbq, *pps, *pps2, *pscale, *pshift;
    __nv_bfloat16 *pwh, *pwl;
    cudaGetSymbolAddress((void**)&px,     g_x);
    cudaGetSymbolAddress((void**)&pqkv,   g_qkv);
    cudaGetSymbolAddress((void**)&po,     g_o);
    cudaGetSymbolAddress((void**)&pt,     g_t);
    cudaGetSymbolAddress((void**)&ph,     g_h);
    cudaGetSymbolAddress((void**)&pbq,    g_bqkv);
    cudaGetSymbolAddress((void**)&pwh,    g_wth);
    cudaGetSymbolAddress((void**)&pwl,    g_wtl);
    cudaGetSymbolAddress((void**)&pps,    g_ps);
    cudaGetSymbolAddress((void**)&pps2,   g_ps2);
    cudaGetSymbolAddress((void**)&pscale, g_scale);
    cudaGetSymbolAddress((void**)&pshift, g_shift);

    const int elem_grid = (TT * EE) / 256;

    embed_kernel<<<elem_grid, 256>>>(s, dd, e_w, e_b, ep_w, ep_b, px);
    pack_bias<<<(3 * QKV + 255) / 256, 256>>>(bq, bk, bv, pbq);
    pack_all<<<(3 * 196608) / 256, 256>>>(Wq, Wk, Wv, Wo, Wf1, Wf2, pwh, pwl);

    const dim3 gQKV(QKV / 128, TT / 128);   // (3, 404)
    const dim3 gE(1, TT / 128);             // (1, 404)
    const dim3 gF(FF / 128, TT / 128);      // (4, 404)

    const float* curS = nullptr;
    const float* curH = nullptr;

    for (int i = 0; i < 3; i++) {
        size_t base = (size_t)i * 196608;

        // qkv = bn(x) @ Wqkv + b
        gemm_mma<<<gQKV, 256>>>(px, pwh + base, pwl + base, pbq + i * QKV,
                                nullptr, pqkv, EE, QKV, 0, curS, curH, nullptr, nullptr);
        attn_kernel<<<BB * MM, 128>>>(pqkv, po);

        // t1 = o @ Wo + bo + bn(x)
        gemm_mma<<<gE, 256>>>(po, pwh + base + 49152, pwl + base + 49152, bo + i * EE,
                              px, pt, EE, EE, 1, nullptr, nullptr, curS, curH);
        bn_partial<<<BN_BLOCKS, 128>>>(pt, pps, pps2);
        bn_finalize<<<1, 128>>>(pps, pps2, g1 + i * EE, be1 + i * EE, pscale, pshift);

        // h = relu(bn1(t1) @ Wf1 + bf1)
        gemm_mma<<<gF, 256>>>(pt, pwh + base + 65536, pwl + base + 65536, bf1 + i * FF,
                              nullptr, ph, EE, FF, 2, pscale, pshift, nullptr, nullptr);
        // t2 = h @ Wf2 + bf2 + bn1(t1)
        gemm_mma<<<gE, 256>>>(ph, pwh + base + 131072, pwl + base + 131072, bf2 + i * EE,
                              pt, px, FF, EE, 1, nullptr, nullptr, pscale, pshift);
        bn_partial<<<BN_BLOCKS, 128>>>(px, pps, pps2);
        bn_finalize<<<1, 128>>>(pps, pps2, g2 + i * EE, be2 + i * EE, pscale, pshift);
        curS = pscale; curH = pshift;
    }
    bn_apply_final<<<elem_grid, 256>>>(px, pscale, pshift, (float*)d_out);
    (void)in_sizes; (void)n_in; (void)out_size;
}

// round 16
// speedup vs baseline: 2.7416x; 1.1441x over previous
#include <cuda_runtime.h>
#include <cuda_bf16.h>
#include <math.h>
#include <cstdint>

// Problem constants
#define BB   512
#define NN   101
#define EE   128
#define MM   8
#define DKK  16
#define TT   (BB * NN)        // 51712 = 404 * 128
#define FF   (4 * EE)         // 512
#define QKV  (3 * EE)         // 384
#define EPS  1e-5f

typedef unsigned long long ull;

// ---------------- device scratch ----------------
__device__ float g_x[TT * EE];
__device__ float g_qkv[TT * QKV];
__device__ float g_o[TT * EE];
__device__ float g_t[TT * EE];
__device__ float g_h[TT * FF];
__device__ float g_bqkv[3 * QKV];
__device__ __nv_bfloat16 g_wth[3 * 196608];   // split-hi weights, [K][N] layout per region
__device__ __nv_bfloat16 g_wtl[3 * 196608];   // split-lo
__device__ float g_ps [256 * EE];
__device__ float g_ps2[256 * EE];
__device__ float g_scale[EE];
__device__ float g_shift[EE];

// ---------------- helpers ----------------
__device__ __forceinline__ ull fma2(ull a, ull b, ull c)
{
    ull d;
    asm("fma.rn.f32x2 %0, %1, %2, %3;" : "=l"(d) : "l"(a), "l"(b), "l"(c));
    return d;
}
__device__ __forceinline__ ull pack2(float x, float y)
{
    ull r;
    asm("mov.b64 %0, {%1, %2};" : "=l"(r) : "f"(x), "f"(y));
    return r;
}
__device__ __forceinline__ float2 unpack2(ull v)
{
    float2 r;
    asm("mov.b64 {%0, %1}, %2;" : "=f"(r.x), "=f"(r.y) : "l"(v));
    return r;
}
__device__ __forceinline__ uint32_t smem_u32(const void* p)
{
    return (uint32_t)__cvta_generic_to_shared(p);
}
__device__ __forceinline__ uint32_t bf2u(__nv_bfloat16 a, __nv_bfloat16 b)
{
    return ((uint32_t)__bfloat16_as_ushort(b) << 16) | __bfloat16_as_ushort(a);
}

__device__ __forceinline__ void ldsm_x4(uint32_t* r, uint32_t addr)
{
    asm volatile("ldmatrix.sync.aligned.m8n8.x4.shared.b16 {%0,%1,%2,%3}, [%4];"
                 : "=r"(r[0]), "=r"(r[1]), "=r"(r[2]), "=r"(r[3]) : "r"(addr));
}
__device__ __forceinline__ void ldsm_x4t(uint32_t* r, uint32_t addr)
{
    asm volatile("ldmatrix.sync.aligned.m8n8.x4.trans.shared.b16 {%0,%1,%2,%3}, [%4];"
                 : "=r"(r[0]), "=r"(r[1]), "=r"(r[2]), "=r"(r[3]) : "r"(addr));
}
__device__ __forceinline__ void mma16816(float* c, const uint32_t* a,
                                         uint32_t b0, uint32_t b1)
{
    asm volatile(
        "mma.sync.aligned.m16n8k16.row.col.f32.bf16.bf16.f32 "
        "{%0,%1,%2,%3}, {%4,%5,%6,%7}, {%8,%9}, {%0,%1,%2,%3};"
        : "+f"(c[0]), "+f"(c[1]), "+f"(c[2]), "+f"(c[3])
        : "r"(a[0]), "r"(a[1]), "r"(a[2]), "r"(a[3]), "r"(b0), "r"(b1));
}

// ---------------- embedding ----------------
__global__ void embed_kernel(const float* __restrict__ s, const int* __restrict__ d,
                             const float* __restrict__ e_w, const float* __restrict__ e_b,
                             const float* __restrict__ ep_w, const float* __restrict__ ep_b,
                             float* __restrict__ x)
{
    int idx = blockIdx.x * 256 + threadIdx.x;
    if (idx >= TT * EE) return;
    int e = idx & (EE - 1);
    int t = idx >> 7;
    int n = t % NN;
    int b = t / NN;
    float s0 = s[(b * NN + n) * 2 + 0];
    float s1 = s[(b * NN + n) * 2 + 1];
    float out;
    if (n == 0) {
        out = s0 * ep_w[e] + s1 * ep_w[EE + e] + ep_b[e];
    } else {
        float dd = (float)d[b * NN + n];
        out = s0 * e_w[e] + s1 * e_w[EE + e] + dd * e_w[2 * EE + e] + e_b[e];
    }
    x[idx] = out;
}

// ---------------- pack: split all weights (keep [K][N] orientation) --------
// per-layer element offsets: qkv@0 (128x384 fused), wo@49152 (128x128),
// wf1@65536 (128x512), wf2@131072 (512x128); layer stride 196608
__global__ void pack_all(const float* __restrict__ Wq, const float* __restrict__ Wk,
                         const float* __restrict__ Wv, const float* __restrict__ Wo,
                         const float* __restrict__ Wf1, const float* __restrict__ Wf2,
                         __nv_bfloat16* __restrict__ hi, __nv_bfloat16* __restrict__ lo)
{
    int idx = blockIdx.x * 256 + threadIdx.x;
    if (idx >= 3 * 196608) return;
    int layer = idx / 196608;
    int r = idx % 196608;
    float v;
    if (r < 49152) {
        int k = r / 384, j = r % 384;
        int sel = j >> 7, n = j & 127;
        const float* W = (sel == 0) ? Wq : (sel == 1) ? Wk : Wv;
        v = W[layer * 16384 + k * 128 + n];
    } else if (r < 65536) {
        v = Wo[layer * 16384 + (r - 49152)];
    } else if (r < 131072) {
        v = Wf1[layer * 65536 + (r - 65536)];
    } else {
        v = Wf2[layer * 65536 + (r - 131072)];
    }
    __nv_bfloat16 h = __float2bfloat16(v);
    __nv_bfloat16 l = __float2bfloat16(v - __bfloat162float(h));
    hi[idx] = h;
    lo[idx] = l;
}

__global__ void pack_bias(const float* __restrict__ bq, const float* __restrict__ bk,
                          const float* __restrict__ bv, float* __restrict__ bout)
{
    int idx = blockIdx.x * 256 + threadIdx.x;
    if (idx >= 3 * QKV) return;
    int i = idx / QKV;
    int j = idx % QKV;
    float v;
    if (j < EE)          v = bq[i * EE + j];
    else if (j < 2 * EE) v = bk[i * EE + (j - EE)];
    else                 v = bv[i * EE + (j - 2 * EE)];
    bout[idx] = v;
}

// ---------------- tensor-core GEMM (mma.sync, split-bf16) ----------------
// C[128t x 128n] = affA(A) @ W + bias [+ affR(res) | relu]
// W given as split hi/lo bf16 in [K][Nout] layout.
#define AST 40     // A smem row stride (bf16 elems) = 80B, conflict-free LDSM
#define BST 136    // B smem row stride (bf16 elems) = 272B, conflict-free LDSM

__global__ __launch_bounds__(256, 2) void gemm_mma(
    const float* __restrict__ A,
    const __nv_bfloat16* __restrict__ Whi, const __nv_bfloat16* __restrict__ Wlo,
    const float* __restrict__ bias, const float* __restrict__ res,
    float* __restrict__ C, int K, int Nout, int mode,
    const float* __restrict__ sA, const float* __restrict__ hA,
    const float* __restrict__ sR, const float* __restrict__ hR)
{
    __shared__ __nv_bfloat16 sAh[128 * AST];
    __shared__ __nv_bfloat16 sAl[128 * AST];
    __shared__ __nv_bfloat16 sBh[32 * BST];
    __shared__ __nv_bfloat16 sBl[32 * BST];

    const int tid  = threadIdx.x;
    const int lane = tid & 31;
    const int wid  = tid >> 5;
    const int warp_m = wid >> 1;          // 0..3
    const int warp_n = wid & 1;           // 0..1
    const int m0 = warp_m * 32;
    const int nb0 = warp_n * 64;
    const int t0 = blockIdx.y * 128;
    const int nblk = blockIdx.x * 128;

    // loader coords
    const int arow  = tid >> 1;           // 0..127
    const int akoff = (tid & 1) * 16;     // 0 or 16
    const int bkrow = tid >> 3;           // 0..31
    const int bnoff = (tid & 7) * 16;     // 0..112

    float acc[2][8][4];
    #pragma unroll
    for (int mi = 0; mi < 2; mi++)
        #pragma unroll
        for (int ni = 0; ni < 8; ni++)
            #pragma unroll
            for (int q = 0; q < 4; q++)
                acc[mi][ni][q] = 0.f;

    const uint32_t sAh_u = smem_u32(sAh);
    const uint32_t sAl_u = smem_u32(sAl);
    const uint32_t sBh_u = smem_u32(sBh);
    const uint32_t sBl_u = smem_u32(sBl);

    const int nCh = K >> 5;
    for (int ch = 0; ch < nCh; ch++) {
        const int k0 = ch << 5;
        if (ch) __syncthreads();

        // ---- A stage: fp32 -> affine -> split hi/lo bf16
        {
            const float* ap = A + (size_t)(t0 + arow) * K + k0 + akoff;
            float vv[16];
            #pragma unroll
            for (int q = 0; q < 4; q++) {
                float4 v = *reinterpret_cast<const float4*>(ap + q * 4);
                vv[q*4+0] = v.x; vv[q*4+1] = v.y; vv[q*4+2] = v.z; vv[q*4+3] = v.w;
            }
            if (sA) {
                #pragma unroll
                for (int q = 0; q < 16; q++) {
                    int kc = k0 + akoff + q;
                    vv[q] = fmaf(vv[q], sA[kc], hA[kc]);
                }
            }
            uint32_t H[8], L[8];
            #pragma unroll
            for (int q = 0; q < 8; q++) {
                __nv_bfloat16 h0 = __float2bfloat16(vv[q*2+0]);
                __nv_bfloat16 h1 = __float2bfloat16(vv[q*2+1]);
                __nv_bfloat16 l0 = __float2bfloat16(vv[q*2+0] - __bfloat162float(h0));
                __nv_bfloat16 l1 = __float2bfloat16(vv[q*2+1] - __bfloat162float(h1));
                H[q] = bf2u(h0, h1);
                L[q] = bf2u(l0, l1);
            }
            uint4* dh = reinterpret_cast<uint4*>(sAh + arow * AST + akoff);
            uint4* dl = reinterpret_cast<uint4*>(sAl + arow * AST + akoff);
            dh[0] = make_uint4(H[0], H[1], H[2], H[3]);
            dh[1] = make_uint4(H[4], H[5], H[6], H[7]);
            dl[0] = make_uint4(L[0], L[1], L[2], L[3]);
            dl[1] = make_uint4(L[4], L[5], L[6], L[7]);
        }
        // ---- B stage: bf16 [k][n] direct copy (coalesced)
        {
            const uint4* bh = reinterpret_cast<const uint4*>(Whi + (size_t)(k0 + bkrow) * Nout + nblk + bnoff);
            const uint4* bl = reinterpret_cast<const uint4*>(Wlo + (size_t)(k0 + bkrow) * Nout + nblk + bnoff);
            uint4* dh = reinterpret_cast<uint4*>(sBh + bkrow * BST + bnoff);
            uint4* dl = reinterpret_cast<uint4*>(sBl + bkrow * BST + bnoff);
            dh[0] = bh[0]; dh[1] = bh[1];
            dl[0] = bl[0]; dl[1] = bl[1];
        }
        __syncthreads();

        // ---- compute: two k16 steps
        #pragma unroll
        for (int ks = 0; ks < 32; ks += 16) {
            uint32_t ah[2][4], al[2][4];
            #pragma unroll
            for (int mi = 0; mi < 2; mi++) {
                uint32_t aoff = (uint32_t)((m0 + mi * 16 + (lane & 15)) * AST
                                           + ks + ((lane >> 4) & 1) * 8) * 2;
                ldsm_x4(ah[mi], sAh_u + aoff);
                ldsm_x4(al[mi], sAl_u + aoff);
            }
            #pragma unroll
            for (int nt = 0; nt < 4; nt++) {
                uint32_t boff = (uint32_t)((ks + (lane & 15)) * BST
                                           + nb0 + nt * 16 + ((lane >> 4) & 1) * 8) * 2;
                uint32_t bh[4], bl[4];
                ldsm_x4t(bh, sBh_u + boff);
                ldsm_x4t(bl, sBl_u + boff);
                #pragma unroll
                for (int mi = 0; mi < 2; mi++) {
                    mma16816(acc[mi][nt*2+0], ah[mi], bh[0], bh[1]);
                    mma16816(acc[mi][nt*2+1], ah[mi], bh[2], bh[3]);
                    mma16816(acc[mi][nt*2+0], ah[mi], bl[0], bl[1]);
                    mma16816(acc[mi][nt*2+1], ah[mi], bl[2], bl[3]);
                    mma16816(acc[mi][nt*2+0], al[mi], bh[0], bh[1]);
                    mma16816(acc[mi][nt*2+1], al[mi], bh[2], bh[3]);
                }
            }
        }
    }

    // ---- epilogue: fragment rows l/4 & l/4+8, cols (l%4)*2,+1
    const int rql = lane >> 2;          // 0..7
    const int cql = (lane & 3) * 2;
    #pragma unroll
    for (int mi = 0; mi < 2; mi++) {
        #pragma unroll
        for (int ni = 0; ni < 8; ni++) {
            int c = nblk + nb0 + ni * 8 + cql;
            float2 b2 = *reinterpret_cast<const float2*>(&bias[c]);
            float2 sr2 = {1.f, 1.f}, hr2 = {0.f, 0.f};
            if (mode == 1 && sR) {
                sr2 = *reinterpret_cast<const float2*>(&sR[c]);
                hr2 = *reinterpret_cast<const float2*>(&hR[c]);
            }
            #pragma unroll
            for (int half = 0; half < 2; half++) {
                int r = t0 + m0 + mi * 16 + rql + half * 8;
                float v0 = acc[mi][ni][half * 2 + 0] + b2.x;
                float v1 = acc[mi][ni][half * 2 + 1] + b2.y;
                if (mode == 1) {
                    float2 r2 = *reinterpret_cast<const float2*>(&res[(size_t)r * Nout + c]);
                    if (sR) {
                        v0 += fmaf(r2.x, sr2.x, hr2.x);
                        v1 += fmaf(r2.y, sr2.y, hr2.y);
                    } else {
                        v0 += r2.x; v1 += r2.y;
                    }
                } else if (mode == 2) {
                    v0 = fmaxf(v0, 0.f);
                    v1 = fmaxf(v1, 0.f);
                }
                float2 out = {v0, v1};
                *reinterpret_cast<float2*>(&C[(size_t)r * Nout + c]) = out;
            }
        }
    }
}

// ---------------- attention v2 (R7-measured): single-pass f32x2 ------------
__global__ __launch_bounds__(128) void attn_kernel(
    const float* __restrict__ QKVb, float* __restrict__ O)
{
    int bh = blockIdx.x;
    int b = bh >> 3;
    int h = bh & 7;
    const size_t rowbase = (size_t)b * NN;
    const int hq = h * DKK;

    __shared__ float4 ksh[NN][4];
    __shared__ float4 vsh[NN][4];
    int tid = threadIdx.x;
    for (int i = tid; i < NN * 4; i += 128) {
        int j = i >> 2, c = i & 3;
        ksh[j][c] = *reinterpret_cast<const float4*>(&QKVb[(rowbase + j) * QKV + EE     + hq + c * 4]);
        vsh[j][c] = *reinterpret_cast<const float4*>(&QKVb[(rowbase + j) * QKV + 2 * EE + hq + c * 4]);
    }
    __syncthreads();

    if (tid < NN) {
        ull qp[8];
        #pragma unroll
        for (int c = 0; c < 4; c++) {
            float4 q4 = *reinterpret_cast<const float4*>(&QKVb[(rowbase + tid) * QKV + hq + c * 4]);
            qp[c * 2 + 0] = pack2(q4.x * 0.25f, q4.y * 0.25f);
            qp[c * 2 + 1] = pack2(q4.z * 0.25f, q4.w * 0.25f);
        }
        const ull z2 = pack2(0.f, 0.f);
        ull oa[8];
        #pragma unroll
        for (int c = 0; c < 8; c++) oa[c] = z2;
        float l = 0.f;

        for (int j = 0; j < NN; j++) {
            const ulonglong2* kr = reinterpret_cast<const ulonglong2*>(&ksh[j][0]);
            ulonglong2 k0 = kr[0], k1 = kr[1];
            ull c0 = fma2(qp[0], k0.x, z2);
            ull c1 = fma2(qp[1], k0.y, z2);
            c0 = fma2(qp[2], k1.x, c0);
            c1 = fma2(qp[3], k1.y, c1);
            const ulonglong2* kr2 = reinterpret_cast<const ulonglong2*>(&ksh[j][2]);
            ulonglong2 k2 = kr2[0], k3 = kr2[1];
            c0 = fma2(qp[4], k2.x, c0);
            c1 = fma2(qp[5], k2.y, c1);
            c0 = fma2(qp[6], k3.x, c0);
            c1 = fma2(qp[7], k3.y, c1);
            float2 f0 = unpack2(c0), f1 = unpack2(c1);
            float sdot = (f0.x + f0.y) + (f1.x + f1.y);
            float p = __expf(sdot);
            l += p;
            ull pp = pack2(p, p);
            const ulonglong2* vr = reinterpret_cast<const ulonglong2*>(&vsh[j][0]);
            ulonglong2 v0 = vr[0], v1 = vr[1];
            oa[0] = fma2(pp, v0.x, oa[0]);
            oa[1] = fma2(pp, v0.y, oa[1]);
            oa[2] = fma2(pp, v1.x, oa[2]);
            oa[3] = fma2(pp, v1.y, oa[3]);
            const ulonglong2* vr2 = reinterpret_cast<const ulonglong2*>(&vsh[j][2]);
            ulonglong2 v2 = vr2[0], v3 = vr2[1];
            oa[4] = fma2(pp, v2.x, oa[4]);
            oa[5] = fma2(pp, v2.y, oa[5]);
            oa[6] = fma2(pp, v3.x, oa[6]);
            oa[7] = fma2(pp, v3.y, oa[7]);
        }
        float inv = 1.0f / l;
        float* orow = &O[(rowbase + tid) * EE + hq];
        #pragma unroll
        for (int c = 0; c < 4; c++) {
            float2 lo = unpack2(oa[c * 2 + 0]);
            float2 hi = unpack2(oa[c * 2 + 1]);
            float4 v = { lo.x * inv, lo.y * inv, hi.x * inv, hi.y * inv };
            *reinterpret_cast<float4*>(&orow[c * 4]) = v;
        }
    }
}

// ---------------- BatchNorm stats (R7-measured) ----------------
#define BN_BLOCKS 256
#define ROWS_PER_BLK (TT / BN_BLOCKS)   // 202
__global__ __launch_bounds__(128) void bn_partial(const float* __restrict__ x,
                                                  float* __restrict__ psum,
                                                  float* __restrict__ psq)
{
    int e = threadIdx.x;
    int blk = blockIdx.x;
    int r0 = blk * ROWS_PER_BLK;
    float s = 0.f, s2 = 0.f;
    #pragma unroll 4
    for (int r = 0; r < ROWS_PER_BLK; r++) {
        float v = x[(size_t)(r0 + r) * EE + e];
        s += v; s2 += v * v;
    }
    psum[blk * EE + e] = s;
    psq [blk * EE + e] = s2;
}

__global__ __launch_bounds__(128) void bn_finalize(const float* __restrict__ psum,
                                                   const float* __restrict__ psq,
                                                   const float* __restrict__ g,
                                                   const float* __restrict__ be,
                                                   float* __restrict__ scale,
                                                   float* __restrict__ shift)
{
    int e = threadIdx.x;
    float s = 0.f, s2 = 0.f;
    #pragma unroll 8
    for (int i = 0; i < BN_BLOCKS; i++) { s += psum[i * EE + e]; s2 += psq[i * EE + e]; }
    float mu = s / (float)TT;
    float var = s2 / (float)TT - mu * mu;
    float sc = rsqrtf(var + EPS) * g[e];
    scale[e] = sc;
    shift[e] = be[e] - mu * sc;
}

__global__ __launch_bounds__(256) void bn_apply_final(const float* __restrict__ x,
                                                      const float* __restrict__ scale,
                                                      const float* __restrict__ shift,
                                                      float* __restrict__ y)
{
    int idx = blockIdx.x * 256 + threadIdx.x;
    if (idx >= TT * EE) return;
    int e = idx & (EE - 1);
    y[idx] = fmaf(x[idx], scale[e], shift[e]);
}

// ---------------- host orchestration ----------------
extern "C" void kernel_launch(void* const* d_in, const int* in_sizes, int n_in,
                              void* d_out, int out_size)
{
    const float* s    = (const float*)d_in[0];
    const int*   dd   = (const int*)  d_in[1];
    const float* e_w  = (const float*)d_in[2];
    const float* e_b  = (const float*)d_in[3];
    const float* ep_w = (const float*)d_in[4];
    const float* ep_b = (const float*)d_in[5];
    const float* Wq   = (const float*)d_in[6];
    const float* bq   = (const float*)d_in[7];
    const float* Wk   = (const float*)d_in[8];
    const float* bk   = (const float*)d_in[9];
    const float* Wv   = (const float*)d_in[10];
    const float* bv   = (const float*)d_in[11];
    const float* Wo   = (const float*)d_in[12];
    const float* bo   = (const float*)d_in[13];
    const float* Wf1  = (const float*)d_in[14];
    const float* bf1  = (const float*)d_in[15];
    const float* Wf2  = (const float*)d_in[16];
    const float* bf2  = (const float*)d_in[17];
    const float* g1   = (const float*)d_in[18];
    const float* be1  = (const float*)d_in[19];
    const float* g2   = (const float*)d_in[20];
    const float* be2  = (const float*)d_in[21];

    float *px, *pqkv, *po, *pt, *ph, *pbq, *pps, *pps2, *pscale, *pshift;
    __nv_bfloat16 *pwh, *pwl;
    cudaGetSymbolAddress((void**)&px,     g_x);
    cudaGetSymbolAddress((void**)&pqkv,   g_qkv);
    cudaGetSymbolAddress((void**)&po,     g_o);
    cudaGetSymbolAddress((void**)&pt,     g_t);
    cudaGetSymbolAddress((void**)&ph,     g_h);
    cudaGetSymbolAddress((void**)&pbq,    g_bqkv);
    cudaGetSymbolAddress((void**)&pwh,    g_wth);
    cudaGetSymbolAddress((void**)&pwl,    g_wtl);
    cudaGetSymbolAddress((void**)&pps,    g_ps);
    cudaGetSymbolAddress((void**)&pps2,   g_ps2);
    cudaGetSymbolAddress((void**)&pscale, g_scale);
    cudaGetSymbolAddress((void**)&pshift, g_shift);

    const int elem_grid = (TT * EE) / 256;

    embed_kernel<<<elem_grid, 256>>>(s, dd, e_w, e_b, ep_w, ep_b, px);
    pack_bias<<<(3 * QKV + 255) / 256, 256>>>(bq, bk, bv, pbq);
    pack_all<<<(3 * 196608) / 256, 256>>>(Wq, Wk, Wv, Wo, Wf1, Wf2, pwh, pwl);

    const dim3 gQKV(QKV / 128, TT / 128);   // (3, 404)
    const dim3 gE(1, TT / 128);             // (1, 404)
    const dim3 gF(FF / 128, TT / 128);      // (4, 404)

    const float* curS = nullptr;
    const float* curH = nullptr;

    for (int i = 0; i < 3; i++) {
        size_t base = (size_t)i * 196608;

        // qkv = bn(x) @ Wqkv + b
        gemm_mma<<<gQKV, 256>>>(px, pwh + base, pwl + base, pbq + i * QKV,
                                nullptr, pqkv, EE, QKV, 0, curS, curH, nullptr, nullptr);
        attn_kernel<<<BB * MM, 128>>>(pqkv, po);

        // t1 = o @ Wo + bo + bn(x)
        gemm_mma<<<gE, 256>>>(po, pwh + base + 49152, pwl + base + 49152, bo + i * EE,
                              px, pt, EE, EE, 1, nullptr, nullptr, curS, curH);
        bn_partial<<<BN_BLOCKS, 128>>>(pt, pps, pps2);
        bn_finalize<<<1, 128>>>(pps, pps2, g1 + i * EE, be1 + i * EE, pscale, pshift);

        // h = relu(bn1(t1) @ Wf1 + bf1)
        gemm_mma<<<gF, 256>>>(pt, pwh + base + 65536, pwl + base + 65536, bf1 + i * FF,
                              nullptr, ph, EE, FF, 2, pscale, pshift, nullptr, nullptr);
        // t2 = h @ Wf2 + bf2 + bn1(t1)
        gemm_mma<<<gE, 256>>>(ph, pwh + base + 131072, pwl + base + 131072, bf2 + i * EE,
                              pt, px, FF, EE, 1, nullptr, nullptr, pscale, pshift);
        bn_partial<<<BN_BLOCKS, 128>>>(px, pps, pps2);
        bn_finalize<<<1, 128>>>(pps, pps2, g2 + i * EE, be2 + i * EE, pscale, pshift);
        curS = pscale; curH = pshift;
    }
    bn_apply_final<<<elem_grid, 256>>>(px, pscale, pshift, (float*)d_out);
    (void)in_sizes; (void)n_in; (void)out_size;
}